// round 10
// baseline (speedup 1.0000x reference)
#include <cuda_runtime.h>
#include <stdint.h>

#define N_NODES 10000
#define N_EDGES 320000
#define N_PAIRS 2048
#define IN_CH   128
#define HIDDEN  512

#define ROW_WB  320
#define ROW_B4  80
#define BMP_U4  ((size_t)N_NODES * ROW_WB / 4)

#define HSIZE   32768
#define HMASK   (HSIZE - 1)

__device__ __align__(16) unsigned int g_B[(size_t)N_NODES * ROW_WB];
__device__ __align__(16) unsigned int g_hk[HSIZE];
__device__ __align__(16) unsigned int g_hc[HSIZE];
__device__ __align__(16) float g_XS[N_PAIRS * 2 * IN_CH];

// ---------------------------------------------------------------------------
__device__ __forceinline__ int detect64(const void* p) {
    const unsigned int* p32 = (const unsigned int*)p;
    int lane = threadIdx.x & 31;
    bool all0 = (p32[2 * lane + 1] | p32[2 * (lane + 32) + 1]) == 0u;
    return __ballot_sync(0xFFFFFFFFu, all0) == 0xFFFFFFFFu;
}
__device__ __forceinline__ long long load_idx(const void* p, int is64, long long j) {
    if (is64) return ((const long long*)p)[j];
    return (long long)((const int*)p)[j];
}

__device__ __forceinline__ void hash_add(unsigned key) {
    unsigned idx = (key * 2654435761u) & HMASK;
    for (;;) {
        unsigned cur = g_hk[idx];
        if (cur == key + 1u) { atomicAdd(&g_hc[idx], 1u); return; }
        if (cur == 0u) {
            unsigned old = atomicCAS(&g_hk[idx], 0u, key + 1u);
            if (old == 0u || old == key + 1u) { atomicAdd(&g_hc[idx], 1u); return; }
        }
        idx = (idx + 1u) & HMASK;
    }
}
__device__ __forceinline__ unsigned hash_get(unsigned key) {
    unsigned idx = (key * 2654435761u) & HMASK;
    for (;;) {
        unsigned cur = g_hk[idx];
        if (cur == 0u) return 0u;
        if (cur == key + 1u) return g_hc[idx];
        idx = (idx + 1u) & HMASK;
    }
}

// ---------------------------------------------------------------------------
// 1) Scatter
// ---------------------------------------------------------------------------
__global__ void scatter_kernel(const void* __restrict__ ei) {
    int is64 = detect64(ei);
    int e = blockIdx.x * blockDim.x + threadIdx.x;
    if (e >= N_EDGES) return;
    long long s = load_idx(ei, is64, e);
    long long d = load_idx(ei, is64, (long long)N_EDGES + e);
    unsigned bd = 1u << (d & 31);
    unsigned bs = 1u << (s & 31);
    unsigned o1 = atomicOr(&g_B[(size_t)s * ROW_WB + (size_t)(d >> 5)], bd);
    unsigned o2 = atomicOr(&g_B[(size_t)d * ROW_WB + (size_t)(s >> 5)], bs);
    if (o1 & bd) hash_add((unsigned)(s * 16384 + d));
    if (o2 & bs) hash_add((unsigned)(d * 16384 + s));
}

// ---------------------------------------------------------------------------
// 2) Pairs: intersect rows, build xs, init out[b] = b2[0]
// ---------------------------------------------------------------------------
__global__ void pairs_kernel(const void* __restrict__ tar,
                             const float* __restrict__ x,
                             const float* __restrict__ b2,
                             float* __restrict__ out) {
    __shared__ int   s_n[512];
    __shared__ float s_w[512];
    __shared__ int   s_cnt;

    int is64 = detect64(tar);
    int b   = blockIdx.x;
    int tid = threadIdx.x;
    if (tid == 0) {
        s_cnt = 0;
        out[b] = b2[0];
    }
    __syncthreads();

    long long ti = load_idx(tar, is64, b);
    long long tj = load_idx(tar, is64, (long long)N_PAIRS + b);

    if (tid < ROW_B4) {
        const uint4* rowi = reinterpret_cast<const uint4*>(&g_B[(size_t)ti * ROW_WB]);
        const uint4* rowj = reinterpret_cast<const uint4*>(&g_B[(size_t)tj * ROW_WB]);
        uint4 a = rowi[tid];
        uint4 q = rowj[tid];
        unsigned int m4[4] = {a.x & q.x, a.y & q.y, a.z & q.z, a.w & q.w};
#pragma unroll
        for (int w = 0; w < 4; w++) {
            unsigned int m = m4[w];
            while (m) {
                int bit = __ffs(m) - 1;
                int n = tid * 128 + w * 32 + bit;
                unsigned ua = 1u + hash_get((unsigned)(ti * 16384 + n));
                unsigned ub = 1u + hash_get((unsigned)(tj * 16384 + n));
                int idx = atomicAdd(&s_cnt, 1);
                if (idx < 512) {
                    s_n[idx] = n;
                    s_w[idx] = (float)(ua * ub);
                }
                m &= m - 1;
            }
        }
    }
    __syncthreads();

    int cnt = s_cnt < 512 ? s_cnt : 512;

    float xi = x[(size_t)ti * IN_CH + tid];
    float xj = x[(size_t)tj * IN_CH + tid];

    float acc = 0.f;
    for (int e = 0; e < cnt; e++)
        acc = fmaf(s_w[e], x[(size_t)s_n[e] * IN_CH + tid], acc);

    g_XS[(size_t)b * (2 * IN_CH) + tid]         = xi * xj;
    g_XS[(size_t)b * (2 * IN_CH) + IN_CH + tid] = acc;
}

// ---------------------------------------------------------------------------
// 3) Fused GEMM v4: BM=64 x BN=32 x BK=32, 128 threads, thread tile 4p x 4h.
//    Grid = 32 x 16 = 512 blocks -> ~3.5 CTAs/SM (fixes occupancy).
//    out[b] += sum_h relu(C+b1)*W2 via atomicAdd (out pre-init by pairs).
// ---------------------------------------------------------------------------
#define BM 64
#define BN 32
#define BK 32
#define KTOT (2 * IN_CH)
#define NTILES (KTOT / BK)   // 8
#define XPITCH 68            // floats per k-row (64 used), 272B = 16B-multiple

__device__ __forceinline__ unsigned long long fma2(
    unsigned long long a, unsigned long long b, unsigned long long c) {
    unsigned long long d;
    asm("fma.rn.f32x2 %0, %1, %2, %3;" : "=l"(d) : "l"(a), "l"(b), "l"(c));
    return d;
}
__device__ __forceinline__ unsigned long long dup2(float w) {
    unsigned long long r;
    asm("mov.b64 %0, {%1, %1};" : "=l"(r) : "r"(__float_as_uint(w)));
    return r;
}

__global__ __launch_bounds__(128)
void mlp_kernel(const float* __restrict__ W1, const float* __restrict__ b1,
                const float* __restrict__ W2, float* __restrict__ out) {
    __shared__ __align__(16) float s_x[BK][XPITCH];   // 8.7 KB
    __shared__ __align__(16) float s_w[BK][BN];       // 4 KB
    __shared__ float s_red[BM][9];                    // 2.3 KB

    int tid = threadIdx.x;
    int tx  = tid & 7;         // h coord (4 h each)
    int ty  = tid >> 3;        // p coord (4 p each)
    int p0  = ty * 4;
    int b0  = (blockIdx.x & 31) * BM;
    int h0  = (blockIdx.x >> 5) * BN;

    float4 xr[4];
    float4 wr[2];

    // prefetch tile 0
#pragma unroll
    for (int l = 0; l < 4; l++) {
        int fi = tid + l * 128;          // 0..511
        int p = fi >> 3, c = fi & 7;
        xr[l] = *(const float4*)&g_XS[(size_t)(b0 + p) * KTOT + c * 4];
    }
#pragma unroll
    for (int l = 0; l < 2; l++) {
        int fi = tid + l * 128;          // 0..255
        int row = fi >> 3, c4 = fi & 7;
        wr[l] = *(const float4*)&W1[(size_t)row * HIDDEN + h0 + c4 * 4];
    }

    unsigned long long acc2[4][2];   // [hh][pp], pp ull = 2 pairs
#pragma unroll
    for (int i = 0; i < 4; i++) { acc2[i][0] = 0ull; acc2[i][1] = 0ull; }

    for (int t = 0; t < NTILES; t++) {
        // store prefetched tile (xs transposed)
#pragma unroll
        for (int l = 0; l < 4; l++) {
            int fi = tid + l * 128;
            int p = fi >> 3, c = fi & 7;
            s_x[c * 4 + 0][p] = xr[l].x;
            s_x[c * 4 + 1][p] = xr[l].y;
            s_x[c * 4 + 2][p] = xr[l].z;
            s_x[c * 4 + 3][p] = xr[l].w;
        }
#pragma unroll
        for (int l = 0; l < 2; l++) {
            int fi = tid + l * 128;
            int row = fi >> 3, c4 = fi & 7;
            *(float4*)&s_w[row][c4 * 4] = wr[l];
        }
        __syncthreads();

        // prefetch next tile
        if (t + 1 < NTILES) {
            int k0 = (t + 1) * BK;
#pragma unroll
            for (int l = 0; l < 4; l++) {
                int fi = tid + l * 128;
                int p = fi >> 3, c = fi & 7;
                xr[l] = *(const float4*)&g_XS[(size_t)(b0 + p) * KTOT + k0 + c * 4];
            }
#pragma unroll
            for (int l = 0; l < 2; l++) {
                int fi = tid + l * 128;
                int row = fi >> 3, c4 = fi & 7;
                wr[l] = *(const float4*)&W1[(size_t)(k0 + row) * HIDDEN + h0 + c4 * 4];
            }
        }

#pragma unroll 8
        for (int k = 0; k < BK; k++) {
            ulonglong2 xa = *(const ulonglong2*)&s_x[k][p0];
            float4 wv = *(const float4*)&s_w[k][tx * 4];
            float wf[4] = {wv.x, wv.y, wv.z, wv.w};
#pragma unroll
            for (int hh = 0; hh < 4; hh++) {
                unsigned long long wd = dup2(wf[hh]);
                acc2[hh][0] = fma2(xa.x, wd, acc2[hh][0]);
                acc2[hh][1] = fma2(xa.y, wd, acc2[hh][1]);
            }
        }
        __syncthreads();
    }

    // epilogue: relu + W2 weighting, reduce over this block's 32 h
    float4 b1v = *(const float4*)&b1[h0 + tx * 4];
    float4 w2v = *(const float4*)&W2[h0 + tx * 4];
    float bb[4] = {b1v.x, b1v.y, b1v.z, b1v.w};
    float ww[4] = {w2v.x, w2v.y, w2v.z, w2v.w};

    float pv[4] = {0.f, 0.f, 0.f, 0.f};
#pragma unroll
    for (int hh = 0; hh < 4; hh++) {
#pragma unroll
        for (int pp = 0; pp < 2; pp++) {
            union { unsigned long long u; float2 f; } cv;
            cv.u = acc2[hh][pp];
            pv[2 * pp]     += fmaxf(cv.f.x + bb[hh], 0.f) * ww[hh];
            pv[2 * pp + 1] += fmaxf(cv.f.y + bb[hh], 0.f) * ww[hh];
        }
    }
#pragma unroll
    for (int q = 0; q < 4; q++)
        s_red[p0 + q][tx] = pv[q];
    __syncthreads();

    if (tid < BM) {
        float s = 0.f;
#pragma unroll
        for (int q = 0; q < 8; q++) s += s_red[tid][q];
        atomicAdd(&out[b0 + tid], s);
    }
}

// ---------------------------------------------------------------------------
// 4) Streaming clear: whole bitmap + hash
// ---------------------------------------------------------------------------
__global__ void clear_kernel() {
    size_t i = (size_t)blockIdx.x * blockDim.x + threadIdx.x;
    size_t nthreads = (size_t)gridDim.x * blockDim.x;

    uint4 z = make_uint4(0u, 0u, 0u, 0u);
    uint4* bp = reinterpret_cast<uint4*>(g_B);
    for (size_t w = i; w < BMP_U4; w += nthreads)
        bp[w] = z;

    if (i < HSIZE / 4) {
        reinterpret_cast<uint4*>(g_hk)[i] = z;
        reinterpret_cast<uint4*>(g_hc)[i] = z;
    }
}

// ---------------------------------------------------------------------------
// launch (single stream, serial)
// ---------------------------------------------------------------------------
extern "C" void kernel_launch(void* const* d_in, const int* in_sizes, int n_in,
                              void* d_out, int out_size) {
    const float* x   = (const float*)d_in[0];
    const void*  ei  = d_in[1];
    const void*  tar = d_in[2];
    const float* W1  = (const float*)d_in[3];
    const float* b1  = (const float*)d_in[4];
    const float* W2  = (const float*)d_in[5];
    const float* b2  = (const float*)d_in[6];
    float*       out = (float*)d_out;

    (void)in_sizes; (void)n_in; (void)out_size;

    scatter_kernel<<<(N_EDGES + 255) / 256, 256>>>(ei);
    pairs_kernel<<<N_PAIRS, 128>>>(tar, x, b2, out);
    mlp_kernel<<<512, 128>>>(W1, b1, W2, out);
    clear_kernel<<<1184, 256>>>();
}

// round 11
// speedup vs baseline: 1.0444x; 1.0444x over previous
#include <cuda_runtime.h>
#include <stdint.h>

#define N_NODES 10000
#define N_EDGES 320000
#define N_PAIRS 2048
#define IN_CH   128
#define HIDDEN  512

#define ROW_WB  320
#define ROW_B4  80
#define BMP_U4  ((size_t)N_NODES * ROW_WB / 4)

#define HSIZE   32768
#define HMASK   (HSIZE - 1)

__device__ __align__(16) unsigned int g_B[(size_t)N_NODES * ROW_WB];
__device__ __align__(16) unsigned int g_hk[HSIZE];
__device__ __align__(16) unsigned int g_hc[HSIZE];
__device__ __align__(16) float g_XS[N_PAIRS * 2 * IN_CH];

// ---------------------------------------------------------------------------
__device__ __forceinline__ int detect64(const void* p) {
    const unsigned int* p32 = (const unsigned int*)p;
    int lane = threadIdx.x & 31;
    bool all0 = (p32[2 * lane + 1] | p32[2 * (lane + 32) + 1]) == 0u;
    return __ballot_sync(0xFFFFFFFFu, all0) == 0xFFFFFFFFu;
}
__device__ __forceinline__ long long load_idx(const void* p, int is64, long long j) {
    if (is64) return ((const long long*)p)[j];
    return (long long)((const int*)p)[j];
}

__device__ __forceinline__ void hash_add(unsigned key) {
    unsigned idx = (key * 2654435761u) & HMASK;
    for (;;) {
        unsigned cur = g_hk[idx];
        if (cur == key + 1u) { atomicAdd(&g_hc[idx], 1u); return; }
        if (cur == 0u) {
            unsigned old = atomicCAS(&g_hk[idx], 0u, key + 1u);
            if (old == 0u || old == key + 1u) { atomicAdd(&g_hc[idx], 1u); return; }
        }
        idx = (idx + 1u) & HMASK;
    }
}
__device__ __forceinline__ unsigned hash_get(unsigned key) {
    unsigned idx = (key * 2654435761u) & HMASK;
    for (;;) {
        unsigned cur = g_hk[idx];
        if (cur == 0u) return 0u;
        if (cur == key + 1u) return g_hc[idx];
        idx = (idx + 1u) & HMASK;
    }
}

// ---------------------------------------------------------------------------
// 1) Scatter
// ---------------------------------------------------------------------------
__global__ void scatter_kernel(const void* __restrict__ ei) {
    int is64 = detect64(ei);
    int e = blockIdx.x * blockDim.x + threadIdx.x;
    if (e >= N_EDGES) return;
    long long s = load_idx(ei, is64, e);
    long long d = load_idx(ei, is64, (long long)N_EDGES + e);
    unsigned bd = 1u << (d & 31);
    unsigned bs = 1u << (s & 31);
    unsigned o1 = atomicOr(&g_B[(size_t)s * ROW_WB + (size_t)(d >> 5)], bd);
    unsigned o2 = atomicOr(&g_B[(size_t)d * ROW_WB + (size_t)(s >> 5)], bs);
    if (o1 & bd) hash_add((unsigned)(s * 16384 + d));
    if (o2 & bs) hash_add((unsigned)(d * 16384 + s));
}

// ---------------------------------------------------------------------------
// 2) Pairs: intersect rows, build xs, init out[b] = b2[0]
// ---------------------------------------------------------------------------
__global__ void pairs_kernel(const void* __restrict__ tar,
                             const float* __restrict__ x,
                             const float* __restrict__ b2,
                             float* __restrict__ out) {
    __shared__ int   s_n[512];
    __shared__ float s_w[512];
    __shared__ int   s_cnt;

    int is64 = detect64(tar);
    int b   = blockIdx.x;
    int tid = threadIdx.x;
    if (tid == 0) {
        s_cnt = 0;
        out[b] = b2[0];
    }
    __syncthreads();

    long long ti = load_idx(tar, is64, b);
    long long tj = load_idx(tar, is64, (long long)N_PAIRS + b);

    if (tid < ROW_B4) {
        const uint4* rowi = reinterpret_cast<const uint4*>(&g_B[(size_t)ti * ROW_WB]);
        const uint4* rowj = reinterpret_cast<const uint4*>(&g_B[(size_t)tj * ROW_WB]);
        uint4 a = rowi[tid];
        uint4 q = rowj[tid];
        unsigned int m4[4] = {a.x & q.x, a.y & q.y, a.z & q.z, a.w & q.w};
#pragma unroll
        for (int w = 0; w < 4; w++) {
            unsigned int m = m4[w];
            while (m) {
                int bit = __ffs(m) - 1;
                int n = tid * 128 + w * 32 + bit;
                unsigned ua = 1u + hash_get((unsigned)(ti * 16384 + n));
                unsigned ub = 1u + hash_get((unsigned)(tj * 16384 + n));
                int idx = atomicAdd(&s_cnt, 1);
                if (idx < 512) {
                    s_n[idx] = n;
                    s_w[idx] = (float)(ua * ub);
                }
                m &= m - 1;
            }
        }
    }
    __syncthreads();

    int cnt = s_cnt < 512 ? s_cnt : 512;

    float xi = x[(size_t)ti * IN_CH + tid];
    float xj = x[(size_t)tj * IN_CH + tid];

    float acc = 0.f;
    for (int e = 0; e < cnt; e++)
        acc = fmaf(s_w[e], x[(size_t)s_n[e] * IN_CH + tid], acc);

    g_XS[(size_t)b * (2 * IN_CH) + tid]         = xi * xj;
    g_XS[(size_t)b * (2 * IN_CH) + IN_CH + tid] = acc;
}

// ---------------------------------------------------------------------------
// 3) Fused GEMM v5: SAME tiles as R7 (BM=128 x BN=64 x BK=32, grid 128)
//    but 512 threads/block (16 warps/SM) with thread tile 4p x 4h.
// ---------------------------------------------------------------------------
#define BM 128
#define BN 64
#define BK 32
#define KTOT (2 * IN_CH)
#define NTILES (KTOT / BK)   // 8
#define XPITCH 132           // floats per k-row (128 used), 528B (16B multiple)

__device__ __forceinline__ unsigned long long fma2(
    unsigned long long a, unsigned long long b, unsigned long long c) {
    unsigned long long d;
    asm("fma.rn.f32x2 %0, %1, %2, %3;" : "=l"(d) : "l"(a), "l"(b), "l"(c));
    return d;
}
__device__ __forceinline__ unsigned long long dup2(float w) {
    unsigned long long r;
    asm("mov.b64 %0, {%1, %1};" : "=l"(r) : "r"(__float_as_uint(w)));
    return r;
}

__global__ __launch_bounds__(512, 1)
void mlp_kernel(const float* __restrict__ W1, const float* __restrict__ b1,
                const float* __restrict__ W2, float* __restrict__ out) {
    __shared__ __align__(16) float s_x[BK][XPITCH];   // 16.9 KB
    __shared__ __align__(16) float s_w[BK][BN];       // 8 KB
    __shared__ float s_red[BM][16];                   // 8 KB

    int tid = threadIdx.x;
    int tx  = tid & 15;          // h coord: 4 h each (16*4 = 64)
    int ty  = tid >> 4;          // p coord: 4 p each (32*4 = 128)
    int p0  = ty * 4;
    int b0  = (blockIdx.x >> 3) * BM;   // 8 consecutive blocks share pair tile
    int h0  = (blockIdx.x & 7) * BN;

    float4 xr[2];
    float4 wr[1];

    // prefetch tile 0
#pragma unroll
    for (int l = 0; l < 2; l++) {
        int fi = tid + l * 512;          // float4 index in 128x32 tile (1024)
        int p = fi >> 3, c = fi & 7;
        xr[l] = *(const float4*)&g_XS[(size_t)(b0 + p) * KTOT + c * 4];
    }
    {
        int row = tid >> 4, c4 = tid & 15;   // float4 index in 32x64 tile (512)
        wr[0] = *(const float4*)&W1[(size_t)row * HIDDEN + h0 + c4 * 4];
    }

    unsigned long long acc2[4][2];   // [hh][q]: q-th pair-pair (p0+2q, p0+2q+1)
#pragma unroll
    for (int i = 0; i < 4; i++) { acc2[i][0] = 0ull; acc2[i][1] = 0ull; }

    for (int t = 0; t < NTILES; t++) {
        // store prefetched tile (xs transposed)
#pragma unroll
        for (int l = 0; l < 2; l++) {
            int fi = tid + l * 512;
            int p = fi >> 3, c = fi & 7;
            s_x[c * 4 + 0][p] = xr[l].x;
            s_x[c * 4 + 1][p] = xr[l].y;
            s_x[c * 4 + 2][p] = xr[l].z;
            s_x[c * 4 + 3][p] = xr[l].w;
        }
        {
            int row = tid >> 4, c4 = tid & 15;
            *(float4*)&s_w[row][c4 * 4] = wr[0];
        }
        __syncthreads();

        // prefetch next tile
        if (t + 1 < NTILES) {
            int k0 = (t + 1) * BK;
#pragma unroll
            for (int l = 0; l < 2; l++) {
                int fi = tid + l * 512;
                int p = fi >> 3, c = fi & 7;
                xr[l] = *(const float4*)&g_XS[(size_t)(b0 + p) * KTOT + k0 + c * 4];
            }
            {
                int row = tid >> 4, c4 = tid & 15;
                wr[0] = *(const float4*)&W1[(size_t)(k0 + row) * HIDDEN + h0 + c4 * 4];
            }
        }

#pragma unroll 8
        for (int k = 0; k < BK; k++) {
            ulonglong2 xa = *(const ulonglong2*)&s_x[k][p0];   // 4 pairs
            float4 wv = *(const float4*)&s_w[k][tx * 4];       // 4 h
            float wf[4] = {wv.x, wv.y, wv.z, wv.w};
#pragma unroll
            for (int hh = 0; hh < 4; hh++) {
                unsigned long long wd = dup2(wf[hh]);
                acc2[hh][0] = fma2(xa.x, wd, acc2[hh][0]);
                acc2[hh][1] = fma2(xa.y, wd, acc2[hh][1]);
            }
        }
        __syncthreads();
    }

    // epilogue: relu + W2 weighting, reduce over this block's 64 h
    float4 b1v = *(const float4*)&b1[h0 + tx * 4];
    float4 w2v = *(const float4*)&W2[h0 + tx * 4];
    float bb[4] = {b1v.x, b1v.y, b1v.z, b1v.w};
    float ww[4] = {w2v.x, w2v.y, w2v.z, w2v.w};

    float pv[4] = {0.f, 0.f, 0.f, 0.f};
#pragma unroll
    for (int hh = 0; hh < 4; hh++) {
#pragma unroll
        for (int q = 0; q < 2; q++) {
            union { unsigned long long u; float2 f; } cv;
            cv.u = acc2[hh][q];
            pv[2 * q]     += fmaxf(cv.f.x + bb[hh], 0.f) * ww[hh];
            pv[2 * q + 1] += fmaxf(cv.f.y + bb[hh], 0.f) * ww[hh];
        }
    }
#pragma unroll
    for (int q = 0; q < 4; q++)
        s_red[p0 + q][tx] = pv[q];
    __syncthreads();

    if (tid < BM) {
        float s = 0.f;
#pragma unroll
        for (int q = 0; q < 16; q++) s += s_red[tid][q];
        atomicAdd(&out[b0 + tid], s);
    }
}

// ---------------------------------------------------------------------------
// 4) Streaming clear: whole bitmap + hash
// ---------------------------------------------------------------------------
__global__ void clear_kernel() {
    size_t i = (size_t)blockIdx.x * blockDim.x + threadIdx.x;
    size_t nthreads = (size_t)gridDim.x * blockDim.x;

    uint4 z = make_uint4(0u, 0u, 0u, 0u);
    uint4* bp = reinterpret_cast<uint4*>(g_B);
    for (size_t w = i; w < BMP_U4; w += nthreads)
        bp[w] = z;

    if (i < HSIZE / 4) {
        reinterpret_cast<uint4*>(g_hk)[i] = z;
        reinterpret_cast<uint4*>(g_hc)[i] = z;
    }
}

// ---------------------------------------------------------------------------
// launch (single stream, serial)
// ---------------------------------------------------------------------------
extern "C" void kernel_launch(void* const* d_in, const int* in_sizes, int n_in,
                              void* d_out, int out_size) {
    const float* x   = (const float*)d_in[0];
    const void*  ei  = d_in[1];
    const void*  tar = d_in[2];
    const float* W1  = (const float*)d_in[3];
    const float* b1  = (const float*)d_in[4];
    const float* W2  = (const float*)d_in[5];
    const float* b2  = (const float*)d_in[6];
    float*       out = (float*)d_out;

    (void)in_sizes; (void)n_in; (void)out_size;

    scatter_kernel<<<(N_EDGES + 255) / 256, 256>>>(ei);
    pairs_kernel<<<N_PAIRS, 128>>>(tar, x, b2, out);
    mlp_kernel<<<128, 512>>>(W1, b1, W2, out);
    clear_kernel<<<1184, 256>>>();
}

// round 12
// speedup vs baseline: 1.1646x; 1.1151x over previous
#include <cuda_runtime.h>
#include <stdint.h>

#define N_NODES 10000
#define N_EDGES 320000
#define N_PAIRS 2048
#define IN_CH   128
#define HIDDEN  512

#define ROW_WB  320
#define ROW_B4  80
#define BMP_U4  ((size_t)N_NODES * ROW_WB / 4)   // 800000 uint4

#define HSIZE   32768
#define HMASK   (HSIZE - 1)

__device__ __align__(16) unsigned int g_B[(size_t)N_NODES * ROW_WB];
__device__ __align__(16) unsigned int g_hk[HSIZE];
__device__ __align__(16) unsigned int g_hc[HSIZE];
__device__ __align__(16) float g_XS[N_PAIRS * 2 * IN_CH];

// ---------------------------------------------------------------------------
__device__ __forceinline__ int detect64(const void* p) {
    const unsigned int* p32 = (const unsigned int*)p;
    int lane = threadIdx.x & 31;
    bool all0 = (p32[2 * lane + 1] | p32[2 * (lane + 32) + 1]) == 0u;
    return __ballot_sync(0xFFFFFFFFu, all0) == 0xFFFFFFFFu;
}
__device__ __forceinline__ long long load_idx(const void* p, int is64, long long j) {
    if (is64) return ((const long long*)p)[j];
    return (long long)((const int*)p)[j];
}

__device__ __forceinline__ void hash_add(unsigned key) {
    unsigned idx = (key * 2654435761u) & HMASK;
    for (;;) {
        unsigned cur = g_hk[idx];
        if (cur == key + 1u) { atomicAdd(&g_hc[idx], 1u); return; }
        if (cur == 0u) {
            unsigned old = atomicCAS(&g_hk[idx], 0u, key + 1u);
            if (old == 0u || old == key + 1u) { atomicAdd(&g_hc[idx], 1u); return; }
        }
        idx = (idx + 1u) & HMASK;
    }
}
__device__ __forceinline__ unsigned hash_get(unsigned key) {
    unsigned idx = (key * 2654435761u) & HMASK;
    for (;;) {
        unsigned cur = g_hk[idx];
        if (cur == 0u) return 0u;
        if (cur == key + 1u) return g_hc[idx];
        idx = (idx + 1u) & HMASK;
    }
}

// ---------------------------------------------------------------------------
// 1) Scatter
// ---------------------------------------------------------------------------
__global__ void scatter_kernel(const void* __restrict__ ei) {
    int is64 = detect64(ei);
    int e = blockIdx.x * blockDim.x + threadIdx.x;
    if (e >= N_EDGES) return;
    long long s = load_idx(ei, is64, e);
    long long d = load_idx(ei, is64, (long long)N_EDGES + e);
    unsigned bd = 1u << (d & 31);
    unsigned bs = 1u << (s & 31);
    unsigned o1 = atomicOr(&g_B[(size_t)s * ROW_WB + (size_t)(d >> 5)], bd);
    unsigned o2 = atomicOr(&g_B[(size_t)d * ROW_WB + (size_t)(s >> 5)], bs);
    if (o1 & bd) hash_add((unsigned)(s * 16384 + d));
    if (o2 & bs) hash_add((unsigned)(d * 16384 + s));
}

// ---------------------------------------------------------------------------
// 2) Pairs: intersect rows, build xs, init out[b] = b2[0]
// ---------------------------------------------------------------------------
__global__ void pairs_kernel(const void* __restrict__ tar,
                             const float* __restrict__ x,
                             const float* __restrict__ b2,
                             float* __restrict__ out) {
    __shared__ int   s_n[512];
    __shared__ float s_w[512];
    __shared__ int   s_cnt;

    int is64 = detect64(tar);
    int b   = blockIdx.x;
    int tid = threadIdx.x;
    if (tid == 0) {
        s_cnt = 0;
        out[b] = b2[0];
    }
    __syncthreads();

    long long ti = load_idx(tar, is64, b);
    long long tj = load_idx(tar, is64, (long long)N_PAIRS + b);

    if (tid < ROW_B4) {
        const uint4* rowi = reinterpret_cast<const uint4*>(&g_B[(size_t)ti * ROW_WB]);
        const uint4* rowj = reinterpret_cast<const uint4*>(&g_B[(size_t)tj * ROW_WB]);
        uint4 a = rowi[tid];
        uint4 q = rowj[tid];
        unsigned int m4[4] = {a.x & q.x, a.y & q.y, a.z & q.z, a.w & q.w};
#pragma unroll
        for (int w = 0; w < 4; w++) {
            unsigned int m = m4[w];
            while (m) {
                int bit = __ffs(m) - 1;
                int n = tid * 128 + w * 32 + bit;
                unsigned ua = 1u + hash_get((unsigned)(ti * 16384 + n));
                unsigned ub = 1u + hash_get((unsigned)(tj * 16384 + n));
                int idx = atomicAdd(&s_cnt, 1);
                if (idx < 512) {
                    s_n[idx] = n;
                    s_w[idx] = (float)(ua * ub);
                }
                m &= m - 1;
            }
        }
    }
    __syncthreads();

    int cnt = s_cnt < 512 ? s_cnt : 512;

    float xi = x[(size_t)ti * IN_CH + tid];
    float xj = x[(size_t)tj * IN_CH + tid];

    float acc = 0.f;
    for (int e = 0; e < cnt; e++)
        acc = fmaf(s_w[e], x[(size_t)s_n[e] * IN_CH + tid], acc);

    g_XS[(size_t)b * (2 * IN_CH) + tid]         = xi * xj;
    g_XS[(size_t)b * (2 * IN_CH) + IN_CH + tid] = acc;
}

// ---------------------------------------------------------------------------
// 3) Fused GEMM (R7's v2, unchanged hot loop) + atomicAdd epilogue
//    + per-block bitmap/hash clear tail (replaces clear_kernel).
// ---------------------------------------------------------------------------
#define BM 128
#define BN 64
#define BK 32
#define KTOT (2 * IN_CH)
#define NTILES (KTOT / BK)   // 8

__device__ __forceinline__ unsigned long long fma2(
    unsigned long long a, unsigned long long b, unsigned long long c) {
    unsigned long long d;
    asm("fma.rn.f32x2 %0, %1, %2, %3;" : "=l"(d) : "l"(a), "l"(b), "l"(c));
    return d;
}
__device__ __forceinline__ unsigned long long dup2(float w) {
    unsigned long long r;
    asm("mov.b64 %0, {%1, %1};" : "=l"(r) : "r"(__float_as_uint(w)));
    return r;
}

__global__ __launch_bounds__(256, 1)
void mlp_kernel(const float* __restrict__ W1, const float* __restrict__ b1,
                const float* __restrict__ W2, float* __restrict__ out) {
    __shared__ __align__(16) float s_x[BK][BM + 4];
    __shared__ __align__(16) float s_w[BK][BN];
    __shared__ float s_red[BM][17];

    int tid = threadIdx.x;
    int tx  = tid & 15;
    int ty  = tid >> 4;
    int b0  = (blockIdx.x & 15) * BM;
    int h0  = (blockIdx.x >> 4) * BN;

    float4 xr[4];
    float4 wr[2];
#pragma unroll
    for (int l = 0; l < 4; l++) {
        int fi = tid + l * 256;
        int p  = fi >> 3;
        int kc = fi & 7;
        xr[l] = *reinterpret_cast<const float4*>(&g_XS[(size_t)(b0 + p) * KTOT + kc * 4]);
    }
#pragma unroll
    for (int l = 0; l < 2; l++) {
        int fi = tid + l * 256;
        int kk = fi >> 4;
        int cc = (fi & 15) * 4;
        wr[l] = *reinterpret_cast<const float4*>(&W1[(size_t)kk * HIDDEN + h0 + cc]);
    }

    unsigned long long acc2[4][4];
#pragma unroll
    for (int i = 0; i < 4; i++)
#pragma unroll
        for (int j = 0; j < 4; j++) acc2[i][j] = 0ull;

    for (int t = 0; t < NTILES; t++) {
#pragma unroll
        for (int l = 0; l < 4; l++) {
            int fi = tid + l * 256;
            int p  = fi >> 3;
            int kc = fi & 7;
            s_x[kc * 4 + 0][p] = xr[l].x;
            s_x[kc * 4 + 1][p] = xr[l].y;
            s_x[kc * 4 + 2][p] = xr[l].z;
            s_x[kc * 4 + 3][p] = xr[l].w;
        }
#pragma unroll
        for (int l = 0; l < 2; l++) {
            int fi = tid + l * 256;
            int kk = fi >> 4;
            int cc = (fi & 15) * 4;
            *reinterpret_cast<float4*>(&s_w[kk][cc]) = wr[l];
        }
        __syncthreads();

        if (t + 1 < NTILES) {
            int k0 = (t + 1) * BK;
#pragma unroll
            for (int l = 0; l < 4; l++) {
                int fi = tid + l * 256;
                int p  = fi >> 3;
                int kc = fi & 7;
                xr[l] = *reinterpret_cast<const float4*>(
                    &g_XS[(size_t)(b0 + p) * KTOT + k0 + kc * 4]);
            }
#pragma unroll
            for (int l = 0; l < 2; l++) {
                int fi = tid + l * 256;
                int kk = fi >> 4;
                int cc = (fi & 15) * 4;
                wr[l] = *reinterpret_cast<const float4*>(
                    &W1[(size_t)(k0 + kk) * HIDDEN + h0 + cc]);
            }
        }

#pragma unroll 8
        for (int k = 0; k < BK; k++) {
            float4 wv = *reinterpret_cast<const float4*>(&s_w[k][tx * 4]);
            unsigned long long wd[4];
            wd[0] = dup2(wv.x); wd[1] = dup2(wv.y);
            wd[2] = dup2(wv.z); wd[3] = dup2(wv.w);
            ulonglong2 xa = *reinterpret_cast<const ulonglong2*>(&s_x[k][ty * 8]);
            ulonglong2 xb = *reinterpret_cast<const ulonglong2*>(&s_x[k][ty * 8 + 4]);
            unsigned long long xp[4] = {xa.x, xa.y, xb.x, xb.y};
#pragma unroll
            for (int pp = 0; pp < 4; pp++)
#pragma unroll
                for (int hh = 0; hh < 4; hh++)
                    acc2[pp][hh] = fma2(xp[pp], wd[hh], acc2[pp][hh]);
        }
        __syncthreads();
    }

    float4 b1v = *reinterpret_cast<const float4*>(&b1[h0 + tx * 4]);
    float4 w2v = *reinterpret_cast<const float4*>(&W2[h0 + tx * 4]);
    float bb[4] = {b1v.x, b1v.y, b1v.z, b1v.w};
    float ww[4] = {w2v.x, w2v.y, w2v.z, w2v.w};

    float pval[8];
#pragma unroll
    for (int pp = 0; pp < 4; pp++) {
        float lo = 0.f, hi = 0.f;
#pragma unroll
        for (int hh = 0; hh < 4; hh++) {
            union { unsigned long long u; float2 f; } cv;
            cv.u = acc2[pp][hh];
            lo += fmaxf(cv.f.x + bb[hh], 0.f) * ww[hh];
            hi += fmaxf(cv.f.y + bb[hh], 0.f) * ww[hh];
        }
        pval[pp * 2 + 0] = lo;
        pval[pp * 2 + 1] = hi;
    }

#pragma unroll
    for (int q = 0; q < 8; q++)
        s_red[ty * 8 + q][tx] = pval[q];
    __syncthreads();

    if (tid < BM) {
        float s = 0.f;
#pragma unroll
        for (int t = 0; t < 16; t++) s += s_red[tid][t];
        atomicAdd(&out[b0 + tid], s);
    }

    // -------- clear tail: this block zeroes its 1/128 slice of bitmap + hash
    {
        uint4 z = make_uint4(0u, 0u, 0u, 0u);
        uint4* bp = reinterpret_cast<uint4*>(g_B);
        size_t start = (size_t)blockIdx.x * (BMP_U4 / 128);   // 6250 per block
        size_t end   = start + (BMP_U4 / 128);
        for (size_t w = start + tid; w < end; w += 256)
            bp[w] = z;

        int hs = blockIdx.x * (HSIZE / 4 / 128);              // 64 uint4 per block
        if (tid < HSIZE / 4 / 128) {
            reinterpret_cast<uint4*>(g_hk)[hs + tid] = z;
            reinterpret_cast<uint4*>(g_hc)[hs + tid] = z;
        }
    }
}

// ---------------------------------------------------------------------------
// launch (single stream, serial, 3 kernels)
// ---------------------------------------------------------------------------
extern "C" void kernel_launch(void* const* d_in, const int* in_sizes, int n_in,
                              void* d_out, int out_size) {
    const float* x   = (const float*)d_in[0];
    const void*  ei  = d_in[1];
    const void*  tar = d_in[2];
    const float* W1  = (const float*)d_in[3];
    const float* b1  = (const float*)d_in[4];
    const float* W2  = (const float*)d_in[5];
    const float* b2  = (const float*)d_in[6];
    float*       out = (float*)d_out;

    (void)in_sizes; (void)n_in; (void)out_size;

    scatter_kernel<<<(N_EDGES + 255) / 256, 256>>>(ei);
    pairs_kernel<<<N_PAIRS, 128>>>(tar, x, b2, out);
    mlp_kernel<<<128, 256>>>(W1, b1, W2, out);
}